// round 12
// baseline (speedup 1.0000x reference)
#include <cuda_runtime.h>

#define GG    49
#define CQ    64
#define NEGV  (-1e20f)

// Softmax probabilities: [n][49][16]; pH slots 0..6 (7=0), pW slots 8..14 (15=0).
__device__ float g_p[512 * GG * 16];
__device__ int   g_ready[512];   // zero-init; reset to 0 by last consumer each launch
__device__ int   g_done[512];    // zero-init; consumer count per n

// ---------------------------------------------------------------------------
// Fused kernel. grid = N*5, block = 128, static smem 29792 B, 102-reg cap
// -> 5 blocks/SM (reg-limited), wave 1 = 740 slots >= 512 A-blocks.
//   bid <  N : A-role (logits + softmax for n=bid, two smem passes)
//   bid >= N : B-role (R8-proven output kernel for (n, c-chunk))
// ---------------------------------------------------------------------------
__global__ __launch_bounds__(128, 5) void ax_attn_fused(
    const float* __restrict__ qH, const float* __restrict__ kH,
    const float* __restrict__ qW, const float* __restrict__ kW,
    const float* __restrict__ vH, const float* __restrict__ vW,
    float* __restrict__ out, int N, int Cv)
{
    __shared__ float sm[7448];   // A: sQ[0..3331] sK[3332..6663] sL[6664..7447]
                                 // B: sOut[0..6271]              sP[6664..7447]
    const int bid = blockIdx.x;
    const int tid = threadIdx.x;

    if (bid < N) {
        // ================= A role: n = bid =================
        const int n = bid;
        float* sQ = sm;
        float* sK = sm + 3332;   // transposed [g*7+j][c], row stride 68
        float* sL = sm + 6664;   // 49*16 logits

        #define SCATTER_K1(i4, vk)                                  \
        {                                                           \
            int w = (i4) / 112, r4 = (i4) - w * 112, r = 4 * r4;    \
            int c = r / 7, j = r - 7 * c;                           \
            float av[4] = {(vk).x, (vk).y, (vk).z, (vk).w};         \
            _Pragma("unroll")                                       \
            for (int e = 0; e < 4; e++) {                           \
                sK[(w * 7 + j) * 68 + c] = av[e];                   \
                if (++j == 7) { j = 0; c++; }                       \
            }                                                       \
        }

        #pragma unroll
        for (int pass = 0; pass < 2; pass++) {
            const float4* qg = (const float4*)((pass ? qW : qH) + (size_t)n * 3136);
            const float4* kg = (const float4*)((pass ? kW : kH) + (size_t)n * 3136);

            // stage q (natural, 68-padded rows) + k (transposed scatter)
            #pragma unroll
            for (int u = 0; u < 6; u++) {
                int i4 = tid + u * 128;
                float4 qv = qg[i4];
                float4 kv = kg[i4];
                int g = i4 >> 4, c4 = i4 & 15;
                ((float4*)(sQ + g * 68))[c4] = qv;
                SCATTER_K1(i4, kv);
            }
            if (tid < 16) {
                int i4 = 768 + tid;
                float4 qv = qg[i4];
                float4 kv = kg[i4];
                int g = i4 >> 4, c4 = i4 & 15;
                ((float4*)(sQ + g * 68))[c4] = qv;
                SCATTER_K1(i4, kv);
            }
            __syncthreads();

            // 343 dots over 128 threads
            #pragma unroll
            for (int u = 0; u < 3; u++) {
                int idx = tid + u * 128;
                if (idx < 343) {
                    const int a0 = idx / 49;
                    const int r  = idx - a0 * 49;
                    const int a1 = r / 7;
                    const int a2 = r - a1 * 7;
                    const float4* q = (const float4*)(sQ + (a0 * 7 + a1) * 68);
                    const float4* k = (const float4*)(sK + (a0 * 7 + a2) * 68);
                    float s0 = 0.f, s1 = 0.f;
                    #pragma unroll
                    for (int c4 = 0; c4 < 16; c4 += 2) {
                        float4 qa = q[c4],     ka = k[c4];
                        float4 qb = q[c4 + 1], kb = k[c4 + 1];
                        s0 = fmaf(qa.x, ka.x, s0); s0 = fmaf(qa.y, ka.y, s0);
                        s0 = fmaf(qa.z, ka.z, s0); s0 = fmaf(qa.w, ka.w, s0);
                        s1 = fmaf(qb.x, kb.x, s1); s1 = fmaf(qb.y, kb.y, s1);
                        s1 = fmaf(qb.z, kb.z, s1); s1 = fmaf(qb.w, kb.w, s1);
                    }
                    if (pass == 0)
                        sL[(a1 * 7 + a0) * 16 + a2] = (a1 == a2) ? NEGV : (s0 + s1);
                    else
                        sL[(a0 * 7 + a1) * 16 + 8 + a2] = s0 + s1;
                }
            }
            __syncthreads();
        }
        #undef SCATTER_K1

        // softmax over slots {0..6, 8..14}
        if (tid < GG) {
            const float* row = sL + tid * 16;
            float m = row[0];
            #pragma unroll
            for (int i = 1; i < 7; i++)  m = fmaxf(m, row[i]);
            #pragma unroll
            for (int i = 8; i < 15; i++) m = fmaxf(m, row[i]);
            float e[16], sum = 0.f;
            #pragma unroll
            for (int i = 0; i < 7; i++)  { e[i] = __expf(row[i] - m); sum += e[i]; }
            #pragma unroll
            for (int i = 8; i < 15; i++) { e[i] = __expf(row[i] - m); sum += e[i]; }
            float inv = 1.f / sum;
            float4* dst = (float4*)&g_p[((size_t)n * GG + tid) * 16];
            dst[0] = make_float4(e[0] * inv,  e[1] * inv,  e[2] * inv,  e[3] * inv);
            dst[1] = make_float4(e[4] * inv,  e[5] * inv,  e[6] * inv,  0.f);
            dst[2] = make_float4(e[8] * inv,  e[9] * inv,  e[10] * inv, e[11] * inv);
            dst[3] = make_float4(e[12] * inv, e[13] * inv, e[14] * inv, 0.f);
        }
        __threadfence();      // all writers drain their g_p stores
        __syncthreads();
        if (tid == 0) atomicExch(&g_ready[n], 1);   // release flag
        return;
    }

    // ================= B role =================
    const int t  = bid - N;
    const int n  = t % N;
    const int cc = t / N;            // 0..3
    const int c0 = cc * 128;
    const int c  = c0 + tid;
    const int ws = Cv * 7;

    float* sOut = sm;                // 6272
    float* sP   = sm + 6664;         // 784

    const float* bH = vH + (size_t)n * Cv * 49 + (size_t)c * 7;
    const float* bW = vW + (size_t)n * Cv * 49 + (size_t)c * 7;

    // issue vh loads FIRST (independent of p) — latency overlaps the flag wait
    float vh[49];
    #pragma unroll
    for (int w = 0; w < 7; w++)
        #pragma unroll
        for (int j = 0; j < 7; j++)
            vh[w * 7 + j] = bH[w * ws + j];

    // wait for this n's softmax
    if (tid == 0) {
        while (atomicAdd(&g_ready[n], 0) == 0) __nanosleep(64);
        __threadfence();   // acquire
    }
    __syncthreads();

    // stage p to smem
    {
        const float4* pg = (const float4*)&g_p[(size_t)n * GG * 16];
        float4 p0 = pg[tid];
        float4 p1; bool hp1 = (tid < 68);
        if (hp1) p1 = pg[tid + 128];
        ((float4*)sP)[tid] = p0;
        if (hp1) ((float4*)sP)[tid + 128] = p1;
    }
    __syncthreads();

    // consumer accounting: 4th consumer of n resets flags for the next launch
    if (tid == 0) {
        int d = atomicAdd(&g_done[n], 1);
        if (d == 3) {
            g_done[n] = 0;
            __threadfence();
            atomicExch(&g_ready[n], 0);
        }
    }

    #pragma unroll
    for (int h = 0; h < 7; h++) {
        const float* bWh = bW + h * ws;
        float vw0 = bWh[0], vw1 = bWh[1], vw2 = bWh[2], vw3 = bWh[3];
        float vw4 = bWh[4], vw5 = bWh[5], vw6 = bWh[6];
        #pragma unroll
        for (int w = 0; w < 7; w++) {
            const float4* p4 = (const float4*)(sP + (h * 7 + w) * 16);
            float4 a = p4[0], b = p4[1], c4 = p4[2], d4 = p4[3];
            float s = a.x * vh[w * 7 + 0];
            s = fmaf(a.y, vh[w * 7 + 1], s);
            s = fmaf(a.z, vh[w * 7 + 2], s);
            s = fmaf(a.w, vh[w * 7 + 3], s);
            s = fmaf(b.x, vh[w * 7 + 4], s);
            s = fmaf(b.y, vh[w * 7 + 5], s);
            s = fmaf(b.z, vh[w * 7 + 6], s);
            s = fmaf(c4.x, vw0, s);
            s = fmaf(c4.y, vw1, s);
            s = fmaf(c4.z, vw2, s);
            s = fmaf(c4.w, vw3, s);
            s = fmaf(d4.x, vw4, s);
            s = fmaf(d4.y, vw5, s);
            s = fmaf(d4.z, vw6, s);
            sOut[tid * 49 + h * 7 + w] = s;   // stride 49 (coprime 32) -> conflict-free
        }
    }
    __syncthreads();

    // coalesced float4 write-out: sOut[c_local*49 + pos] == out[n, c0+c_local, pos]
    float* dst = out + ((size_t)n * Cv + c0) * GG;
    #pragma unroll
    for (int u = 0; u < 12; u++)
        ((float4*)dst)[tid + u * 128] = ((const float4*)sOut)[tid + u * 128];
    if (tid < 32)
        ((float4*)dst)[1536 + tid] = ((const float4*)sOut)[1536 + tid];
}

// ---------------------------------------------------------------------------
extern "C" void kernel_launch(void* const* d_in, const int* in_sizes, int n_in,
                              void* d_out, int out_size)
{
    const float* qH = (const float*)d_in[0];
    const float* kH = (const float*)d_in[1];
    const float* vH = (const float*)d_in[2];
    const float* qW = (const float*)d_in[3];
    const float* kW = (const float*)d_in[4];
    const float* vW = (const float*)d_in[5];

    const int B  = in_sizes[0] / (7 * CQ);    // 3584
    const int N  = B / 7;                     // 512
    const int Cv = in_sizes[2] / (B * 7);     // 512

    const int nB = Cv / 128;                  // 4 c-chunks
    ax_attn_fused<<<N * (1 + nB), 128>>>(qH, kH, qW, kW, vH, vW, (float*)d_out, N, Cv);
}